// round 14
// baseline (speedup 1.0000x reference)
#include <cuda_runtime.h>
#include <cuda_bf16.h>
#include <cstdint>

#define NUM_USERS 100000
#define NUM_ITEMS 100000
#define N_TOTAL   200000
#define DIM       64
#define E_EDGES   3200000

// single-pass scan: 256 thr x 16 elems = 4096/block; 49 blocks cover 200704
#define SCAN_THR   256
#define SCAN_PER   16
#define SCAN_BLK   ((N_TOTAL + SCAN_THR * SCAN_PER - 1) / (SCAN_THR * SCAN_PER))

#define NPW 4   // nodes per warp in fused layer (W-read amortization)

// ---------------- scratch (device globals: no allocation allowed) ----------
__device__ float g_h   [N_TOTAL * DIM];   // layer-1 output
__device__ int2  g_esrt [E_EDGES];        // dst-sorted: {src, w_bits}
__device__ int   g_cnt [N_TOTAL];         // zeroed by exact-size memset
__device__ int   g_incl[SCAN_BLK + 16];   // zeroed by prep_kernel block 0
__device__ int   g_flag[SCAN_BLK + 16];   // zeroed by prep_kernel block 0
__device__ int   g_off [N_TOTAL];
__device__ int   g_cur [N_TOTAL];
__device__ float g_x   [N_TOTAL * DIM];   // layer-0 input x (concat copy)

// ---------------- branchless dtype sniff (int64 vs int32) ------------------
__device__ __forceinline__ int sniff_is64(const void* ei) {
    const unsigned long long* p = (const unsigned long long*)ei;
    return (p[1] < (unsigned long long)N_TOTAL) &&
           (p[2] < (unsigned long long)N_TOTAL) &&
           (p[3] < (unsigned long long)N_TOTAL);
}

// ---------------- prep: concat copy + dst histogram + chain-state zero -----
__global__ void __launch_bounds__(256) prep_kernel(
        const void* __restrict__ ei,
        const float4* __restrict__ ue, const float4* __restrict__ ie) {
    if (blockIdx.x == 0 && threadIdx.x < SCAN_BLK + 16) {
        g_incl[threadIdx.x] = 0;
        g_flag[threadIdx.x] = 0;
    }

    int is64 = sniff_is64(ei);
    int i = blockIdx.x * blockDim.x + threadIdx.x;
    if (i >= E_EDGES) return;                    // E_EDGES == N_TOTAL*DIM/4

    const int usplit = NUM_USERS * DIM / 4;
    reinterpret_cast<float4*>(g_x)[i] = (i < usplit) ? ue[i] : ie[i - usplit];

    int t;
    if (is64) t = (int)((const long long*)ei)[E_EDGES + i];
    else      t = ((const int*)ei)[E_EDGES + i];
    atomicAdd(&g_cnt[t], 1);
}

// ---------------- single-pass exclusive scan (decoupled chain) -------------
__global__ void __launch_bounds__(SCAN_THR) scan_kernel() {
    __shared__ int s_warp[8];
    __shared__ int s_prefix;
    int t = threadIdx.x;
    int blk = blockIdx.x;
    int lane = t & 31, wid = t >> 5;
    int base = (blk * SCAN_THR + t) * SCAN_PER;

    int v[SCAN_PER];
    int tsum = 0;
    #pragma unroll
    for (int k = 0; k < SCAN_PER; k++) {
        int idx = base + k;
        int c = (idx < N_TOTAL) ? g_cnt[idx] : 0;
        v[k] = tsum;
        tsum += c;
    }

    int ws = tsum;
    #pragma unroll
    for (int d = 1; d < 32; d <<= 1) {
        int n = __shfl_up_sync(0xffffffffu, ws, d);
        if (lane >= d) ws += n;
    }
    if (lane == 31) s_warp[wid] = ws;
    __syncthreads();
    if (wid == 0) {
        int x = (lane < 8) ? s_warp[lane] : 0;
        #pragma unroll
        for (int d = 1; d < 8; d <<= 1) {
            int n = __shfl_up_sync(0xffffffffu, x, d);
            if (lane >= d) x += n;
        }
        if (lane < 8) s_warp[lane] = x;
    }
    __syncthreads();
    int texcl = (ws - tsum) + (wid ? s_warp[wid - 1] : 0);
    int btotal = s_warp[7];

    if (t == 0) {
        int prefix = 0;
        if (blk > 0) {
            while (((volatile int*)g_flag)[blk - 1] == 0) { }
            prefix = g_incl[blk - 1];
        }
        g_incl[blk] = prefix + btotal;
        __threadfence();
        ((volatile int*)g_flag)[blk] = 1;
        s_prefix = prefix;
    }
    __syncthreads();
    int prefix = s_prefix;

    #pragma unroll
    for (int k = 0; k < SCAN_PER; k++) {
        int idx = base + k;
        if (idx < N_TOTAL) {
            int o = prefix + texcl + v[k];
            g_off[idx] = o;
            g_cur[idx] = o;
        }
    }
}

// ---------------- placement: dst-sorted edge list --------------------------
__global__ void __launch_bounds__(256) place_kernel(
        const void* __restrict__ ei, const float* __restrict__ w) {
    int is64 = sniff_is64(ei);
    int i = blockIdx.x * blockDim.x + threadIdx.x;
    if (i >= E_EDGES) return;
    int s, t;
    if (is64) {
        const long long* p = (const long long*)ei;
        s = (int)p[i];
        t = (int)p[E_EDGES + i];
    } else {
        const int* p = (const int*)ei;
        s = p[i];
        t = p[E_EDGES + i];
    }
    int pos = atomicAdd(&g_cur[t], 1);
    g_esrt[pos] = make_int2(s, __float_as_int(w[i]));
}

// ---------------- fused layer: out = 0.5*(x + scatter(x)) @ W + b ----------
// One warp per NPW nodes. Phase 1: aggregate each node into per-warp smem
// rowbuf. Phase 2: matvec all NPW rows together so each Ws LDS is reused
// NPW times (cuts the dominant W-wavefront cost by NPW).
__global__ void __launch_bounds__(256) fused_layer_kernel(
        const float* __restrict__ x, const float* __restrict__ W,
        const float* __restrict__ b, float* __restrict__ out) {
    __shared__ float Ws[DIM * DIM];
    __shared__ float bs[DIM];
    __shared__ float rowbuf[8][NPW][DIM];
    for (int i = threadIdx.x; i < DIM * DIM; i += blockDim.x) Ws[i] = W[i];
    if (threadIdx.x < DIM) bs[threadIdx.x] = b[threadIdx.x];
    __syncthreads();

    int lane  = threadIdx.x & 31;
    int warp  = threadIdx.x >> 5;
    int gwarp = blockIdx.x * 8 + warp;
    int nwarp = gridDim.x * 8;

    const float2* xp = reinterpret_cast<const float2*>(x);
    float bias0 = bs[lane], bias1 = bs[32 + lane];

    // N_TOTAL % NPW == 0, so every group is full when base < N_TOTAL.
    for (int base = gwarp * NPW; base < N_TOTAL; base += nwarp * NPW) {
        // ---- phase 1: aggregate NPW nodes into rowbuf ----
        #pragma unroll 1
        for (int r = 0; r < NPW; r++) {
            int node = base + r;
            float2 acc = xp[(size_t)node * 32 + lane];   // residual term
            int e = g_off[node];
            int end = e + g_cnt[node];
            for (; e + 1 < end; e += 2) {
                int2 d0 = g_esrt[e];
                int2 d1 = g_esrt[e + 1];
                float2 v0 = xp[(size_t)d0.x * 32 + lane];
                float2 v1 = xp[(size_t)d1.x * 32 + lane];
                float w0 = __int_as_float(d0.y);
                float w1 = __int_as_float(d1.y);
                acc.x += w0 * v0.x + w1 * v1.x;
                acc.y += w0 * v0.y + w1 * v1.y;
            }
            if (e < end) {
                int2 d0 = g_esrt[e];
                float2 v0 = xp[(size_t)d0.x * 32 + lane];
                float w0 = __int_as_float(d0.y);
                acc.x += w0 * v0.x;
                acc.y += w0 * v0.y;
            }
            *reinterpret_cast<float2*>(&rowbuf[warp][r][2 * lane]) = acc;
        }
        __syncwarp();

        // ---- phase 2: matvec NPW rows, sharing every Ws load ----
        float a0[NPW], a1[NPW];
        #pragma unroll
        for (int r = 0; r < NPW; r++) { a0[r] = 0.f; a1[r] = 0.f; }

        #pragma unroll
        for (int kk = 0; kk < 16; kk++) {
            float4 v[NPW];
            #pragma unroll
            for (int r = 0; r < NPW; r++)
                v[r] = *reinterpret_cast<const float4*>(&rowbuf[warp][r][kk * 4]);
            int k = kk * 4;
            #pragma unroll
            for (int kv = 0; kv < 4; kv++) {
                float w0 = Ws[(k + kv) * DIM + lane];
                float w1 = Ws[(k + kv) * DIM + 32 + lane];
                #pragma unroll
                for (int r = 0; r < NPW; r++) {
                    float c = (kv == 0) ? v[r].x : (kv == 1) ? v[r].y
                            : (kv == 2) ? v[r].z : v[r].w;
                    a0[r] += c * w0;
                    a1[r] += c * w1;
                }
            }
        }

        #pragma unroll
        for (int r = 0; r < NPW; r++) {
            size_t o = (size_t)(base + r) * DIM;
            out[o + lane]      = 0.5f * a0[r] + bias0;
            out[o + 32 + lane] = 0.5f * a1[r] + bias1;
        }
        __syncwarp();
    }
}

// ---------------- launch ----------------------------------------------------
extern "C" void kernel_launch(void* const* d_in, const int* in_sizes, int n_in,
                              void* d_out, int out_size) {
    const void*  ei = d_in[0];
    const float* ew = (const float*)d_in[1];
    const float* ue = (const float*)d_in[2];
    const float* ie = (const float*)d_in[3];
    const float* W1 = (const float*)d_in[4];
    const float* b1 = (const float*)d_in[5];
    const float* W2 = (const float*)d_in[6];
    const float* b2 = (const float*)d_in[7];
    float* out = (float*)d_out;

    float *px, *ph;
    int   *pcnt;
    cudaGetSymbolAddress((void**)&px,   g_x);
    cudaGetSymbolAddress((void**)&ph,   g_h);
    cudaGetSymbolAddress((void**)&pcnt, g_cnt);

    cudaMemsetAsync(pcnt, 0, N_TOTAL * sizeof(int));

    // kernel #1: fused concat copy + dst histogram + chain-state zero
    prep_kernel<<<(E_EDGES + 255) / 256, 256>>>(
        ei, (const float4*)ue, (const float4*)ie);

    // kernel #2: single-pass exclusive scan
    scan_kernel<<<SCAN_BLK, SCAN_THR>>>();

    // kernel #3: dst-sorted edge list
    place_kernel<<<(E_EDGES + 255) / 256, 256>>>(ei, ew);

    const int fl_blocks = 2048;   // 8 warps/block, NPW nodes/warp, grid-stride

    // kernel #4: fused layer 1 (x -> h)   <-- ncu capture slot
    fused_layer_kernel<<<fl_blocks, 256>>>(px, W1, b1, ph);

    // kernel #5: fused layer 2 (h -> out)
    fused_layer_kernel<<<fl_blocks, 256>>>(ph, W2, b2, out);
}

// round 16
// speedup vs baseline: 1.4422x; 1.4422x over previous
#include <cuda_runtime.h>
#include <cuda_bf16.h>
#include <cstdint>

#define NUM_USERS 100000
#define NUM_ITEMS 100000
#define N_TOTAL   200000
#define DIM       64
#define E_EDGES   3200000

// single-pass scan: 256 thr x 16 elems = 4096/block; 49 blocks cover 200704
#define SCAN_THR   256
#define SCAN_PER   16
#define SCAN_BLK   ((N_TOTAL + SCAN_THR * SCAN_PER - 1) / (SCAN_THR * SCAN_PER))

typedef unsigned int       u32;
typedef unsigned long long u64;

// ---------------- scratch (device globals: no allocation allowed) ----------
__device__ float g_agg [N_TOTAL * DIM];   // aggregated rows
__device__ float g_h   [N_TOTAL * DIM];   // layer-1 output
__device__ int2  g_esrt [E_EDGES];        // dst-sorted: {src, w_bits}
__device__ int   g_cnt [N_TOTAL];         // zeroed by exact-size memset
__device__ int   g_incl[SCAN_BLK + 16];   // zeroed by prep_kernel block 0
__device__ int   g_flag[SCAN_BLK + 16];   // zeroed by prep_kernel block 0
__device__ int   g_off [N_TOTAL];
__device__ int   g_cur [N_TOTAL];
__device__ float g_x   [N_TOTAL * DIM];   // layer-0 input x (concat copy)

// ---------------- helpers ---------------------------------------------------
__device__ __forceinline__ u32 smem_u32(const void* p) {
    u32 a;
    asm("{ .reg .u64 t; cvta.to.shared.u64 t, %1; cvt.u32.u64 %0, t; }"
        : "=r"(a) : "l"(p));
    return a;
}
#define SW128(off) ((off) ^ (((off) >> 3) & 0x70))

__device__ __forceinline__ void ldsm_x4(u32& r0, u32& r1, u32& r2, u32& r3, u32 addr) {
    asm volatile("ldmatrix.sync.aligned.m8n8.x4.shared.b16 {%0,%1,%2,%3}, [%4];"
                 : "=r"(r0), "=r"(r1), "=r"(r2), "=r"(r3) : "r"(addr));
}
__device__ __forceinline__ void ldsm_x2(u32& r0, u32& r1, u32 addr) {
    asm volatile("ldmatrix.sync.aligned.m8n8.x2.shared.b16 {%0,%1}, [%2];"
                 : "=r"(r0), "=r"(r1) : "r"(addr));
}
__device__ __forceinline__ void mma_bf16(float* d, const u32* a, const u32* b) {
    asm volatile(
        "mma.sync.aligned.m16n8k16.row.col.f32.bf16.bf16.f32 "
        "{%0,%1,%2,%3}, {%4,%5,%6,%7}, {%8,%9}, {%0,%1,%2,%3};"
        : "+f"(d[0]), "+f"(d[1]), "+f"(d[2]), "+f"(d[3])
        : "r"(a[0]), "r"(a[1]), "r"(a[2]), "r"(a[3]), "r"(b[0]), "r"(b[1]));
}
__device__ __forceinline__ u32 pack_bf16(float x, float y) {
    __nv_bfloat16 bx = __float2bfloat16(x);
    __nv_bfloat16 by = __float2bfloat16(y);
    return ((u32)__bfloat16_as_ushort(by) << 16) | __bfloat16_as_ushort(bx);
}

// ---------------- branchless dtype sniff (int64 vs int32) ------------------
__device__ __forceinline__ int sniff_is64(const void* ei) {
    const u64* p = (const u64*)ei;
    return (p[1] < (u64)N_TOTAL) && (p[2] < (u64)N_TOTAL) && (p[3] < (u64)N_TOTAL);
}

// ---------------- prep: concat copy + dst histogram + chain-state zero -----
__global__ void __launch_bounds__(256) prep_kernel(
        const void* __restrict__ ei,
        const float4* __restrict__ ue, const float4* __restrict__ ie) {
    if (blockIdx.x == 0 && threadIdx.x < SCAN_BLK + 16) {
        g_incl[threadIdx.x] = 0;
        g_flag[threadIdx.x] = 0;
    }
    int is64 = sniff_is64(ei);
    int i = blockIdx.x * blockDim.x + threadIdx.x;
    if (i >= E_EDGES) return;

    const int usplit = NUM_USERS * DIM / 4;
    reinterpret_cast<float4*>(g_x)[i] = (i < usplit) ? ue[i] : ie[i - usplit];

    int t;
    if (is64) t = (int)((const long long*)ei)[E_EDGES + i];
    else      t = ((const int*)ei)[E_EDGES + i];
    atomicAdd(&g_cnt[t], 1);
}

// ---------------- single-pass exclusive scan (decoupled chain) -------------
__global__ void __launch_bounds__(SCAN_THR) scan_kernel() {
    __shared__ int s_warp[8];
    __shared__ int s_prefix;
    int t = threadIdx.x;
    int blk = blockIdx.x;
    int lane = t & 31, wid = t >> 5;
    int base = (blk * SCAN_THR + t) * SCAN_PER;

    int v[SCAN_PER];
    int tsum = 0;
    #pragma unroll
    for (int k = 0; k < SCAN_PER; k++) {
        int idx = base + k;
        int c = (idx < N_TOTAL) ? g_cnt[idx] : 0;
        v[k] = tsum;
        tsum += c;
    }
    int ws = tsum;
    #pragma unroll
    for (int d = 1; d < 32; d <<= 1) {
        int n = __shfl_up_sync(0xffffffffu, ws, d);
        if (lane >= d) ws += n;
    }
    if (lane == 31) s_warp[wid] = ws;
    __syncthreads();
    if (wid == 0) {
        int x = (lane < 8) ? s_warp[lane] : 0;
        #pragma unroll
        for (int d = 1; d < 8; d <<= 1) {
            int n = __shfl_up_sync(0xffffffffu, x, d);
            if (lane >= d) x += n;
        }
        if (lane < 8) s_warp[lane] = x;
    }
    __syncthreads();
    int texcl = (ws - tsum) + (wid ? s_warp[wid - 1] : 0);
    int btotal = s_warp[7];

    if (t == 0) {
        int prefix = 0;
        if (blk > 0) {
            while (((volatile int*)g_flag)[blk - 1] == 0) { }
            prefix = g_incl[blk - 1];
        }
        g_incl[blk] = prefix + btotal;
        __threadfence();
        ((volatile int*)g_flag)[blk] = 1;
        s_prefix = prefix;
    }
    __syncthreads();
    int prefix = s_prefix;

    #pragma unroll
    for (int k = 0; k < SCAN_PER; k++) {
        int idx = base + k;
        if (idx < N_TOTAL) {
            int o = prefix + texcl + v[k];
            g_off[idx] = o;
            g_cur[idx] = o;
        }
    }
}

// ---------------- placement: dst-sorted edge list --------------------------
__global__ void __launch_bounds__(256) place_kernel(
        const void* __restrict__ ei, const float* __restrict__ w) {
    int is64 = sniff_is64(ei);
    int i = blockIdx.x * blockDim.x + threadIdx.x;
    if (i >= E_EDGES) return;
    int s, t;
    if (is64) {
        const long long* p = (const long long*)ei;
        s = (int)p[i];
        t = (int)p[E_EDGES + i];
    } else {
        const int* p = (const int*)ei;
        s = p[i];
        t = p[E_EDGES + i];
    }
    int pos = atomicAdd(&g_cur[t], 1);
    g_esrt[pos] = make_int2(s, __float_as_int(w[i]));
}

// ---------------- segmented aggregation (measured-86us R8 shape) -----------
__global__ void __launch_bounds__(256) aggregate_kernel(
        const float* __restrict__ x, float* __restrict__ out) {
    int warp = (blockIdx.x * blockDim.x + threadIdx.x) >> 5;
    int lane = threadIdx.x & 31;
    if (warp >= N_TOTAL) return;

    int start = g_off[warp];
    int cnt   = g_cnt[warp];
    const float2* xp = reinterpret_cast<const float2*>(x);

    float2 acc = xp[(size_t)warp * 32 + lane];   // residual term

    int e = start, end = start + cnt;
    for (; e + 1 < end; e += 2) {
        int2 d0 = g_esrt[e];
        int2 d1 = g_esrt[e + 1];
        float2 v0 = xp[(size_t)d0.x * 32 + lane];
        float2 v1 = xp[(size_t)d1.x * 32 + lane];
        float w0 = __int_as_float(d0.y);
        float w1 = __int_as_float(d1.y);
        acc.x += w0 * v0.x + w1 * v1.x;
        acc.y += w0 * v0.y + w1 * v1.y;
    }
    if (e < end) {
        int2 d0 = g_esrt[e];
        float2 v0 = xp[(size_t)d0.x * 32 + lane];
        float w0 = __int_as_float(d0.y);
        acc.x += w0 * v0.x;
        acc.y += w0 * v0.y;
    }
    reinterpret_cast<float2*>(out)[(size_t)warp * 32 + lane] = acc;
}

// ---------------- linear via mma.sync: out = in @ (0.5W) + b ---------------
// CTA = 128 rows. bf16 hi/lo 3-product split, fp32 accumulate.
// smem: Ahi[128x64 bf16 SW128] | Alo | Bhi(W^T 64x64) | Blo   (48KB)
#define LOFF_AHI 0
#define LOFF_ALO 16384
#define LOFF_BHI 32768
#define LOFF_BLO 40960
#define LIN_SMEM 49152

__global__ void __launch_bounds__(256) linear_mma_kernel(
        const float* __restrict__ in, const float* __restrict__ W,
        const float* __restrict__ b, float* __restrict__ out) {
    extern __shared__ char smem[];
    u32 sb = smem_u32(smem);
    int tid  = threadIdx.x;
    int lane = tid & 31;
    int wid  = tid >> 5;
    int tile = blockIdx.x * 128;

    // ---- convert A rows -> bf16 hi/lo, SW128 ----
    for (int i = tid; i < 128 * 16; i += 256) {
        int row = i >> 4, c = i & 15;          // c: float4 chunk (k = 4c..4c+3)
        int grow = tile + row;
        float4 v = make_float4(0.f, 0.f, 0.f, 0.f);
        if (grow < N_TOTAL)
            v = *reinterpret_cast<const float4*>(in + (size_t)grow * DIM + c * 4);
        float hx = __bfloat162float(__float2bfloat16(v.x));
        float hy = __bfloat162float(__float2bfloat16(v.y));
        float hz = __bfloat162float(__float2bfloat16(v.z));
        float hw = __bfloat162float(__float2bfloat16(v.w));
        u32 h0 = pack_bf16(v.x, v.y), h1 = pack_bf16(v.z, v.w);
        u32 l0 = pack_bf16(v.x - hx, v.y - hy), l1 = pack_bf16(v.z - hz, v.w - hw);
        u32 off = SW128((u32)(row * 128 + c * 8));
        *reinterpret_cast<u32*>(smem + LOFF_AHI + off)     = h0;
        *reinterpret_cast<u32*>(smem + LOFF_AHI + off + 4) = h1;
        *reinterpret_cast<u32*>(smem + LOFF_ALO + off)     = l0;
        *reinterpret_cast<u32*>(smem + LOFF_ALO + off + 4) = l1;
    }
    // ---- convert 0.5*W -> W^T[n][k] bf16 hi/lo, SW128 ----
    for (int i = tid; i < DIM * DIM; i += 256) {
        int k = i >> 6, n = i & 63;
        float w5 = 0.5f * W[i];                // W[k][n]
        __nv_bfloat16 hi = __float2bfloat16(w5);
        float lof = w5 - __bfloat162float(hi);
        u32 off = SW128((u32)(n * 128 + k * 2));
        *reinterpret_cast<unsigned short*>(smem + LOFF_BHI + off) = __bfloat16_as_ushort(hi);
        *reinterpret_cast<unsigned short*>(smem + LOFF_BLO + off) = __bfloat16_as_ushort(__float2bfloat16(lof));
    }
    __syncthreads();

    // ---- per warp: rows [wid*16, wid*16+16) x all 64 cols ----
    // A fragments for all 4 k-steps, hi & lo (kept in regs).
    u32 ahi[4][4], alo[4][4];
    {
        int arow = wid * 16 + (lane & 15);
        int acolb = (lane >> 4) * 16;          // +8 cols = +16 bytes
        #pragma unroll
        for (int ks = 0; ks < 4; ks++) {
            u32 off = SW128((u32)(arow * 128 + ks * 32 + acolb));
            ldsm_x4(ahi[ks][0], ahi[ks][1], ahi[ks][2], ahi[ks][3], sb + LOFF_AHI + off);
            ldsm_x4(alo[ks][0], alo[ks][1], alo[ks][2], alo[ks][3], sb + LOFF_ALO + off);
        }
    }

    #pragma unroll 1
    for (int nt = 0; nt < 8; nt++) {
        // B fragments for this n-tile, all k-steps
        u32 bhi[4][2], blo[4][2];
        int brow = nt * 8 + (lane & 7);
        int bcolb = ((lane >> 3) & 1) * 16;    // second 8x8 = +8 k = +16B
        #pragma unroll
        for (int ks = 0; ks < 4; ks++) {
            u32 off = SW128((u32)(brow * 128 + ks * 32 + bcolb));
            ldsm_x2(bhi[ks][0], bhi[ks][1], sb + LOFF_BHI + off);
            ldsm_x2(blo[ks][0], blo[ks][1], sb + LOFF_BLO + off);
        }

        float d[4] = {0.f, 0.f, 0.f, 0.f};
        #pragma unroll
        for (int ks = 0; ks < 4; ks++) {
            mma_bf16(d, ahi[ks], bhi[ks]);
            mma_bf16(d, alo[ks], bhi[ks]);
            mma_bf16(d, ahi[ks], blo[ks]);
        }

        int col  = nt * 8 + (lane & 3) * 2;
        float2 bb = *reinterpret_cast<const float2*>(b + col);
        int row0 = tile + wid * 16 + (lane >> 2);
        int row1 = row0 + 8;
        if (row0 < N_TOTAL)
            *reinterpret_cast<float2*>(out + (size_t)row0 * DIM + col) =
                make_float2(d[0] + bb.x, d[1] + bb.y);
        if (row1 < N_TOTAL)
            *reinterpret_cast<float2*>(out + (size_t)row1 * DIM + col) =
                make_float2(d[2] + bb.x, d[3] + bb.y);
    }
}

// ---------------- launch ----------------------------------------------------
extern "C" void kernel_launch(void* const* d_in, const int* in_sizes, int n_in,
                              void* d_out, int out_size) {
    const void*  ei = d_in[0];
    const float* ew = (const float*)d_in[1];
    const float* ue = (const float*)d_in[2];
    const float* ie = (const float*)d_in[3];
    const float* W1 = (const float*)d_in[4];
    const float* b1 = (const float*)d_in[5];
    const float* W2 = (const float*)d_in[6];
    const float* b2 = (const float*)d_in[7];
    float* out = (float*)d_out;

    float *px, *pagg, *ph;
    int   *pcnt;
    cudaGetSymbolAddress((void**)&px,   g_x);
    cudaGetSymbolAddress((void**)&pagg, g_agg);
    cudaGetSymbolAddress((void**)&ph,   g_h);
    cudaGetSymbolAddress((void**)&pcnt, g_cnt);

    cudaMemsetAsync(pcnt, 0, N_TOTAL * sizeof(int));

    // kernel #1: fused concat copy + dst histogram + chain-state zero
    prep_kernel<<<(E_EDGES + 255) / 256, 256>>>(
        ei, (const float4*)ue, (const float4*)ie);

    // kernel #2: single-pass exclusive scan
    scan_kernel<<<SCAN_BLK, SCAN_THR>>>();

    // kernel #3: dst-sorted edge list
    place_kernel<<<(E_EDGES + 255) / 256, 256>>>(ei, ew);

    cudaFuncSetAttribute(linear_mma_kernel,
                         cudaFuncAttributeMaxDynamicSharedMemorySize, LIN_SMEM);

    const int agg_blocks = (N_TOTAL * 32 + 255) / 256;   // 1 warp per node
    const int lin_blocks = (N_TOTAL + 127) / 128;        // 1563 tiles

    // kernel #4: layer-1 aggregate  <-- ncu capture slot
    aggregate_kernel<<<agg_blocks, 256>>>(px, pagg);
    // kernel #5: layer-1 linear (mma.sync)
    linear_mma_kernel<<<lin_blocks, 256, LIN_SMEM>>>(pagg, W1, b1, ph);
    // kernel #6: layer-2 aggregate
    aggregate_kernel<<<agg_blocks, 256>>>(ph, pagg);
    // kernel #7: layer-2 linear
    linear_mma_kernel<<<lin_blocks, 256, LIN_SMEM>>>(pagg, W2, b2, out);
}

// round 17
// speedup vs baseline: 1.5728x; 1.0906x over previous
#include <cuda_runtime.h>
#include <cuda_bf16.h>
#include <cuda_fp16.h>
#include <cstdint>

#define NUM_USERS 100000
#define NUM_ITEMS 100000
#define N_TOTAL   200000
#define DIM       64
#define E_EDGES   3200000

// single-pass scan: 256 thr x 16 elems = 4096/block; 49 blocks cover 200704
#define SCAN_THR   256
#define SCAN_PER   16
#define SCAN_BLK   ((N_TOTAL + SCAN_THR * SCAN_PER - 1) / (SCAN_THR * SCAN_PER))

typedef unsigned int       u32;
typedef unsigned long long u64;

// ---------------- scratch (device globals: no allocation allowed) ----------
__device__ float  g_agg [N_TOTAL * DIM];  // aggregated rows (fp32, GEMM input)
__device__ __half g_xh  [N_TOTAL * DIM];  // layer-0 features, fp16
__device__ __half g_hh  [N_TOTAL * DIM];  // layer-1 output, fp16
__device__ int2   g_esrt [E_EDGES];       // dst-sorted: {src, w_bits}
__device__ int    g_cnt [N_TOTAL];        // zeroed by exact-size memset
__device__ int    g_incl[SCAN_BLK + 16];  // zeroed by prep_kernel block 0
__device__ int    g_flag[SCAN_BLK + 16];  // zeroed by prep_kernel block 0
__device__ int    g_off [N_TOTAL];
__device__ int    g_cur [N_TOTAL];

// ---------------- helpers ---------------------------------------------------
__device__ __forceinline__ u32 smem_u32(const void* p) {
    u32 a;
    asm("{ .reg .u64 t; cvta.to.shared.u64 t, %1; cvt.u32.u64 %0, t; }"
        : "=r"(a) : "l"(p));
    return a;
}
#define SW128(off) ((off) ^ (((off) >> 3) & 0x70))

__device__ __forceinline__ void ldsm_x4(u32& r0, u32& r1, u32& r2, u32& r3, u32 addr) {
    asm volatile("ldmatrix.sync.aligned.m8n8.x4.shared.b16 {%0,%1,%2,%3}, [%4];"
                 : "=r"(r0), "=r"(r1), "=r"(r2), "=r"(r3) : "r"(addr));
}
__device__ __forceinline__ void ldsm_x2(u32& r0, u32& r1, u32 addr) {
    asm volatile("ldmatrix.sync.aligned.m8n8.x2.shared.b16 {%0,%1}, [%2];"
                 : "=r"(r0), "=r"(r1) : "r"(addr));
}
__device__ __forceinline__ void mma_bf16(float* d, const u32* a, const u32* b) {
    asm volatile(
        "mma.sync.aligned.m16n8k16.row.col.f32.bf16.bf16.f32 "
        "{%0,%1,%2,%3}, {%4,%5,%6,%7}, {%8,%9}, {%0,%1,%2,%3};"
        : "+f"(d[0]), "+f"(d[1]), "+f"(d[2]), "+f"(d[3])
        : "r"(a[0]), "r"(a[1]), "r"(a[2]), "r"(a[3]), "r"(b[0]), "r"(b[1]));
}
__device__ __forceinline__ u32 pack_bf16(float x, float y) {
    __nv_bfloat16 bx = __float2bfloat16(x);
    __nv_bfloat16 by = __float2bfloat16(y);
    return ((u32)__bfloat16_as_ushort(by) << 16) | __bfloat16_as_ushort(bx);
}

// ---------------- branchless dtype sniff (int64 vs int32) ------------------
__device__ __forceinline__ int sniff_is64(const void* ei) {
    const u64* p = (const u64*)ei;
    return (p[1] < (u64)N_TOTAL) && (p[2] < (u64)N_TOTAL) && (p[3] < (u64)N_TOTAL);
}

// ---------------- prep: concat copy (fp16) + dst histogram + chain zero ----
__global__ void __launch_bounds__(256) prep_kernel(
        const void* __restrict__ ei,
        const float4* __restrict__ ue, const float4* __restrict__ ie) {
    if (blockIdx.x == 0 && threadIdx.x < SCAN_BLK + 16) {
        g_incl[threadIdx.x] = 0;
        g_flag[threadIdx.x] = 0;
    }
    int is64 = sniff_is64(ei);
    int i = blockIdx.x * blockDim.x + threadIdx.x;
    if (i >= E_EDGES) return;                    // E_EDGES == N_TOTAL*DIM/4

    const int usplit = NUM_USERS * DIM / 4;
    float4 v = (i < usplit) ? ue[i] : ie[i - usplit];
    __half2 h0 = __floats2half2_rn(v.x, v.y);
    __half2 h1 = __floats2half2_rn(v.z, v.w);
    uint2 packed;
    packed.x = *reinterpret_cast<u32*>(&h0);
    packed.y = *reinterpret_cast<u32*>(&h1);
    reinterpret_cast<uint2*>(g_xh)[i] = packed;  // half4 = 8B

    int t;
    if (is64) t = (int)((const long long*)ei)[E_EDGES + i];
    else      t = ((const int*)ei)[E_EDGES + i];
    atomicAdd(&g_cnt[t], 1);
}

// ---------------- single-pass exclusive scan (decoupled chain) -------------
__global__ void __launch_bounds__(SCAN_THR) scan_kernel() {
    __shared__ int s_warp[8];
    __shared__ int s_prefix;
    int t = threadIdx.x;
    int blk = blockIdx.x;
    int lane = t & 31, wid = t >> 5;
    int base = (blk * SCAN_THR + t) * SCAN_PER;

    int v[SCAN_PER];
    int tsum = 0;
    #pragma unroll
    for (int k = 0; k < SCAN_PER; k++) {
        int idx = base + k;
        int c = (idx < N_TOTAL) ? g_cnt[idx] : 0;
        v[k] = tsum;
        tsum += c;
    }
    int ws = tsum;
    #pragma unroll
    for (int d = 1; d < 32; d <<= 1) {
        int n = __shfl_up_sync(0xffffffffu, ws, d);
        if (lane >= d) ws += n;
    }
    if (lane == 31) s_warp[wid] = ws;
    __syncthreads();
    if (wid == 0) {
        int x = (lane < 8) ? s_warp[lane] : 0;
        #pragma unroll
        for (int d = 1; d < 8; d <<= 1) {
            int n = __shfl_up_sync(0xffffffffu, x, d);
            if (lane >= d) x += n;
        }
        if (lane < 8) s_warp[lane] = x;
    }
    __syncthreads();
    int texcl = (ws - tsum) + (wid ? s_warp[wid - 1] : 0);
    int btotal = s_warp[7];

    if (t == 0) {
        int prefix = 0;
        if (blk > 0) {
            while (((volatile int*)g_flag)[blk - 1] == 0) { }
            prefix = g_incl[blk - 1];
        }
        g_incl[blk] = prefix + btotal;
        __threadfence();
        ((volatile int*)g_flag)[blk] = 1;
        s_prefix = prefix;
    }
    __syncthreads();
    int prefix = s_prefix;

    #pragma unroll
    for (int k = 0; k < SCAN_PER; k++) {
        int idx = base + k;
        if (idx < N_TOTAL) {
            int o = prefix + texcl + v[k];
            g_off[idx] = o;
            g_cur[idx] = o;
        }
    }
}

// ---------------- placement: dst-sorted edge list --------------------------
__global__ void __launch_bounds__(256) place_kernel(
        const void* __restrict__ ei, const float* __restrict__ w) {
    int is64 = sniff_is64(ei);
    int i = blockIdx.x * blockDim.x + threadIdx.x;
    if (i >= E_EDGES) return;
    int s, t;
    if (is64) {
        const long long* p = (const long long*)ei;
        s = (int)p[i];
        t = (int)p[E_EDGES + i];
    } else {
        const int* p = (const int*)ei;
        s = p[i];
        t = p[E_EDGES + i];
    }
    int pos = atomicAdd(&g_cur[t], 1);
    g_esrt[pos] = make_int2(s, __float_as_int(w[i]));
}

// ---------------- segmented aggregation (fp16 gather, fp32 accumulate) -----
// One warp per dst node; half2 per lane -> 128B row = 1 L1 wavefront.
__global__ void __launch_bounds__(256) aggregate_kernel(
        const __half* __restrict__ x, float* __restrict__ out) {
    int warp = (blockIdx.x * blockDim.x + threadIdx.x) >> 5;
    int lane = threadIdx.x & 31;
    if (warp >= N_TOTAL) return;

    int start = g_off[warp];
    int cnt   = g_cnt[warp];
    const __half2* xp = reinterpret_cast<const __half2*>(x);

    float2 acc = __half22float2(xp[(size_t)warp * 32 + lane]);  // residual

    int e = start, end = start + cnt;
    for (; e + 1 < end; e += 2) {
        int2 d0 = g_esrt[e];
        int2 d1 = g_esrt[e + 1];
        float2 v0 = __half22float2(xp[(size_t)d0.x * 32 + lane]);
        float2 v1 = __half22float2(xp[(size_t)d1.x * 32 + lane]);
        float w0 = __int_as_float(d0.y);
        float w1 = __int_as_float(d1.y);
        acc.x += w0 * v0.x + w1 * v1.x;
        acc.y += w0 * v0.y + w1 * v1.y;
    }
    if (e < end) {
        int2 d0 = g_esrt[e];
        float2 v0 = __half22float2(xp[(size_t)d0.x * 32 + lane]);
        float w0 = __int_as_float(d0.y);
        acc.x += w0 * v0.x;
        acc.y += w0 * v0.y;
    }
    reinterpret_cast<float2*>(out)[(size_t)warp * 32 + lane] = acc;
}

// ---------------- linear via mma.sync: dst = in @ (0.5W) + b ---------------
// CTA = 128 rows. bf16 hi/lo 3-product split, fp32 accumulate.
// Writes fp32 (outf) and/or fp16 (outh) depending on layer.
#define LOFF_AHI 0
#define LOFF_ALO 16384
#define LOFF_BHI 32768
#define LOFF_BLO 40960
#define LIN_SMEM 49152

__global__ void __launch_bounds__(256) linear_mma_kernel(
        const float* __restrict__ in, const float* __restrict__ W,
        const float* __restrict__ b, float* __restrict__ outf,
        __half* __restrict__ outh) {
    extern __shared__ char smem[];
    u32 sb = smem_u32(smem);
    int tid  = threadIdx.x;
    int lane = tid & 31;
    int wid  = tid >> 5;
    int tile = blockIdx.x * 128;

    // ---- convert A rows -> bf16 hi/lo, SW128 ----
    for (int i = tid; i < 128 * 16; i += 256) {
        int row = i >> 4, c = i & 15;          // c: float4 chunk (k = 4c..4c+3)
        int grow = tile + row;
        float4 v = make_float4(0.f, 0.f, 0.f, 0.f);
        if (grow < N_TOTAL)
            v = *reinterpret_cast<const float4*>(in + (size_t)grow * DIM + c * 4);
        float hx = __bfloat162float(__float2bfloat16(v.x));
        float hy = __bfloat162float(__float2bfloat16(v.y));
        float hz = __bfloat162float(__float2bfloat16(v.z));
        float hw = __bfloat162float(__float2bfloat16(v.w));
        u32 h0 = pack_bf16(v.x, v.y), h1 = pack_bf16(v.z, v.w);
        u32 l0 = pack_bf16(v.x - hx, v.y - hy), l1 = pack_bf16(v.z - hz, v.w - hw);
        u32 off = SW128((u32)(row * 128 + c * 8));
        *reinterpret_cast<u32*>(smem + LOFF_AHI + off)     = h0;
        *reinterpret_cast<u32*>(smem + LOFF_AHI + off + 4) = h1;
        *reinterpret_cast<u32*>(smem + LOFF_ALO + off)     = l0;
        *reinterpret_cast<u32*>(smem + LOFF_ALO + off + 4) = l1;
    }
    // ---- convert 0.5*W -> W^T[n][k] bf16 hi/lo, SW128 ----
    for (int i = tid; i < DIM * DIM; i += 256) {
        int k = i >> 6, n = i & 63;
        float w5 = 0.5f * W[i];                // W[k][n]
        __nv_bfloat16 hi = __float2bfloat16(w5);
        float lof = w5 - __bfloat162float(hi);
        u32 off = SW128((u32)(n * 128 + k * 2));
        *reinterpret_cast<unsigned short*>(smem + LOFF_BHI + off) = __bfloat16_as_ushort(hi);
        *reinterpret_cast<unsigned short*>(smem + LOFF_BLO + off) = __bfloat16_as_ushort(__float2bfloat16(lof));
    }
    __syncthreads();

    // ---- per warp: rows [wid*16, wid*16+16) x all 64 cols ----
    u32 ahi[4][4], alo[4][4];
    {
        int arow = wid * 16 + (lane & 15);
        int acolb = (lane >> 4) * 16;          // +8 cols = +16 bytes
        #pragma unroll
        for (int ks = 0; ks < 4; ks++) {
            u32 off = SW128((u32)(arow * 128 + ks * 32 + acolb));
            ldsm_x4(ahi[ks][0], ahi[ks][1], ahi[ks][2], ahi[ks][3], sb + LOFF_AHI + off);
            ldsm_x4(alo[ks][0], alo[ks][1], alo[ks][2], alo[ks][3], sb + LOFF_ALO + off);
        }
    }

    #pragma unroll 1
    for (int nt = 0; nt < 8; nt++) {
        u32 bhi[4][2], blo[4][2];
        int brow = nt * 8 + (lane & 7);
        int bcolb = ((lane >> 3) & 1) * 16;    // second 8x8 = +8 k = +16B
        #pragma unroll
        for (int ks = 0; ks < 4; ks++) {
            u32 off = SW128((u32)(brow * 128 + ks * 32 + bcolb));
            ldsm_x2(bhi[ks][0], bhi[ks][1], sb + LOFF_BHI + off);
            ldsm_x2(blo[ks][0], blo[ks][1], sb + LOFF_BLO + off);
        }

        float d[4] = {0.f, 0.f, 0.f, 0.f};
        #pragma unroll
        for (int ks = 0; ks < 4; ks++) {
            mma_bf16(d, ahi[ks], bhi[ks]);
            mma_bf16(d, alo[ks], bhi[ks]);
            mma_bf16(d, ahi[ks], blo[ks]);
        }

        int col  = nt * 8 + (lane & 3) * 2;
        float2 bb = *reinterpret_cast<const float2*>(b + col);
        float2 r0 = make_float2(d[0] + bb.x, d[1] + bb.y);
        float2 r1 = make_float2(d[2] + bb.x, d[3] + bb.y);
        int row0 = tile + wid * 16 + (lane >> 2);
        int row1 = row0 + 8;
        if (outf) {
            if (row0 < N_TOTAL)
                *reinterpret_cast<float2*>(outf + (size_t)row0 * DIM + col) = r0;
            if (row1 < N_TOTAL)
                *reinterpret_cast<float2*>(outf + (size_t)row1 * DIM + col) = r1;
        }
        if (outh) {
            if (row0 < N_TOTAL)
                *reinterpret_cast<__half2*>(outh + (size_t)row0 * DIM + col) =
                    __floats2half2_rn(r0.x, r0.y);
            if (row1 < N_TOTAL)
                *reinterpret_cast<__half2*>(outh + (size_t)row1 * DIM + col) =
                    __floats2half2_rn(r1.x, r1.y);
        }
    }
}

// ---------------- launch ----------------------------------------------------
extern "C" void kernel_launch(void* const* d_in, const int* in_sizes, int n_in,
                              void* d_out, int out_size) {
    const void*  ei = d_in[0];
    const float* ew = (const float*)d_in[1];
    const float* ue = (const float*)d_in[2];
    const float* ie = (const float*)d_in[3];
    const float* W1 = (const float*)d_in[4];
    const float* b1 = (const float*)d_in[5];
    const float* W2 = (const float*)d_in[6];
    const float* b2 = (const float*)d_in[7];
    float* out = (float*)d_out;

    float  *pagg;
    __half *pxh, *phh;
    int    *pcnt;
    cudaGetSymbolAddress((void**)&pagg, g_agg);
    cudaGetSymbolAddress((void**)&pxh,  g_xh);
    cudaGetSymbolAddress((void**)&phh,  g_hh);
    cudaGetSymbolAddress((void**)&pcnt, g_cnt);

    cudaMemsetAsync(pcnt, 0, N_TOTAL * sizeof(int));

    // kernel #1: concat copy (fp16) + dst histogram + chain-state zero
    prep_kernel<<<(E_EDGES + 255) / 256, 256>>>(
        ei, (const float4*)ue, (const float4*)ie);

    // kernel #2: single-pass exclusive scan
    scan_kernel<<<SCAN_BLK, SCAN_THR>>>();

    // kernel #3: dst-sorted edge list
    place_kernel<<<(E_EDGES + 255) / 256, 256>>>(ei, ew);

    cudaFuncSetAttribute(linear_mma_kernel,
                         cudaFuncAttributeMaxDynamicSharedMemorySize, LIN_SMEM);

    const int agg_blocks = (N_TOTAL * 32 + 255) / 256;   // 1 warp per node
    const int lin_blocks = (N_TOTAL + 127) / 128;        // 1563 tiles

    // kernel #4: layer-1 aggregate (fp16 gather)  <-- ncu capture slot
    aggregate_kernel<<<agg_blocks, 256>>>(pxh, pagg);
    // kernel #5: layer-1 linear -> fp16 h only
    linear_mma_kernel<<<lin_blocks, 256, LIN_SMEM>>>(pagg, W1, b1, nullptr, phh);
    // kernel #6: layer-2 aggregate
    aggregate_kernel<<<agg_blocks, 256>>>(phh, pagg);
    // kernel #7: layer-2 linear -> fp32 out
    linear_mma_kernel<<<lin_blocks, 256, LIN_SMEM>>>(pagg, W2, b2, out, nullptr);
}